// round 3
// baseline (speedup 1.0000x reference)
#include <cuda_runtime.h>

#define BATCH 16
#define NCH   128
#define TLEN  8192
#define N1    4103
#define N2    2059
#define N3    1037

// ---- scratch (static device arrays; no allocation) --------------------------
// Reuse: inverse y2 overwrites g_lo2 (dead after fwd L3), y1 overwrites g_lo1
// (dead after fwd L2). Total static scratch ~118 MB.
__device__ float g_lo1[BATCH * N1 * NCH];   // fwd L1 lo; later inv L2 output y1
__device__ float g_hi1[BATCH * N1 * NCH];
__device__ float g_lo2[BATCH * N2 * NCH];   // fwd L2 lo; later inv L3 output y2
__device__ float g_hi2[BATCH * N2 * NCH];
__device__ float g_lo3[BATCH * N3 * NCH];
__device__ float g_hi3[BATCH * N3 * NCH];
__device__ float g_thr[BATCH * NCH];

// ---- sym8 filters (compile-time literals -> imm-form FFMA) ------------------
// dec_lo = d[0..15]; rec_lo[k]=d[15-k]; rec_hi[k]=(-1)^k d[k]; dec_hi[m]=(-1)^(m+1) d[15-m]
#define FILT_RL {  0.0018899503327594609f, -0.0003029205147241331f, -0.01495225833704823f,   \
                   0.003808752013890615f,   0.049137179673607506f,  -0.027219029917056003f,  \
                  -0.05194583810770904f,    0.36444189483533895f,    0.7771857517005235f,    \
                   0.4813596512583722f,    -0.061273359067658524f,  -0.1432942383508097f,    \
                   0.007607487324917605f,   0.03169508781149298f,   -0.0005421323317911481f, \
                  -0.0033824159510061256f }
#define FILT_RH { -0.0033824159510061256f,  0.0005421323317911481f,  0.03169508781149298f,   \
                  -0.007607487324917605f,  -0.1432942383508097f,     0.061273359067658524f,  \
                   0.4813596512583722f,    -0.7771857517005235f,     0.36444189483533895f,   \
                   0.05194583810770904f,   -0.027219029917056003f,  -0.049137179673607506f,  \
                   0.003808752013890615f,   0.01495225833704823f,   -0.0003029205147241331f, \
                  -0.0018899503327594609f }
#define FILT_DLO { -0.0033824159510061256f, -0.0005421323317911481f,  0.03169508781149298f,  \
                    0.007607487324917605f,  -0.1432942383508097f,    -0.061273359067658524f, \
                    0.4813596512583722f,     0.7771857517005235f,     0.36444189483533895f,  \
                   -0.05194583810770904f,   -0.027219029917056003f,   0.049137179673607506f, \
                    0.003808752013890615f,  -0.01495225833704823f,   -0.0003029205147241331f,\
                    0.0018899503327594609f }
#define FILT_DHI { -0.0018899503327594609f, -0.0003029205147241331f,  0.01495225833704823f,  \
                    0.003808752013890615f,  -0.049137179673607506f,  -0.027219029917056003f, \
                    0.05194583810770904f,    0.36444189483533895f,   -0.7771857517005235f,   \
                    0.4813596512583722f,     0.061273359067658524f,  -0.1432942383508097f,   \
                   -0.007607487324917605f,   0.03169508781149298f,    0.0005421323317911481f,\
                   -0.0033824159510061256f }

// 0.85 / 0.6745 * sqrt(2*log(8192))
#define THRSCALE ((float)(0.85 * 4.2452122112874176 / 0.6745))

#define PF 8   // outputs per thread, forward
#define PJ 8   // j-positions per thread, inverse (=> 16 outputs)

// ---- forward analysis: stride-2 16-tap correlation with symmetric pad 14 ----
__global__ __launch_bounds__(256) void fwd_kernel(const float* __restrict__ x0, int level) {
    const float* __restrict__ in;
    float* __restrict__ lo;
    float* __restrict__ hi;
    int nin, nout;
    if (level == 1)      { in = x0;    lo = g_lo1; hi = g_hi1; nin = TLEN; nout = N1; }
    else if (level == 2) { in = g_lo1; lo = g_lo2; hi = g_hi2; nin = N1;   nout = N2; }
    else                 { in = g_lo2; lo = g_lo3; hi = g_hi3; nin = N2;   nout = N3; }

    const int b  = blockIdx.y;
    const int n  = threadIdx.x;
    const int p0 = (blockIdx.x * blockDim.y + threadIdx.y) * PF;
    if (p0 >= nout) return;

    const float RL[16] = FILT_RL;
    const float RH[16] = FILT_RH;

    const float* __restrict__ inb = in + (b * nin) * NCH + n;
    float w[2 * PF + 14];
#pragma unroll
    for (int t = 0; t < 2 * PF + 14; ++t) {
        int i = 2 * p0 - 14 + t;
        if (i < 0)    i = -1 - i;          // left symmetric reflection (pad 14)
        if (i >= nin) i = 2 * nin - 1 - i; // right symmetric reflection (pad <= 15)
        w[t] = inb[i * NCH];
    }

    const int obase = (b * nout + p0) * NCH + n;
#pragma unroll
    for (int e = 0; e < PF; ++e) {
        if (p0 + e < nout) {
            float alo = 0.f, ahi = 0.f;
#pragma unroll
            for (int k = 0; k < 16; ++k) {
                const float v = w[2 * e + k];
                alo += v * RL[k];
                ahi += v * RH[k];
            }
            lo[obase + e * NCH] = alo;
            hi[obase + e * NCH] = ahi;
        }
    }
}

// ---- median of |cd1| per signal: stage bits in smem once, 4 radix passes ----
// 8 consecutive channels per CTA -> every global load is a full 32B sector.
// Exact lower median: rank 2051 (0-based) of 4103.
#define MED_SMEM_BYTES (N1 * 8 * 4)

__global__ __launch_bounds__(256) void med_kernel() {
    extern __shared__ unsigned int sdat[];      // [N1*8], layout p*8 + j
    __shared__ unsigned int cnt[8 * 256];
    __shared__ unsigned int pref[8];
    __shared__ int          krem[8];

    const int b   = blockIdx.y;
    const int n0  = blockIdx.x * 8;
    const int tid = threadIdx.x;
    const int j   = tid & 7;
    const int r   = tid >> 3;   // 0..31

    // stage |cd1| bit patterns (nonneg float bits order == float order)
    const float* __restrict__ base = g_hi1 + (b * N1) * NCH + n0 + j;
    for (int p = r; p < N1; p += 32)
        sdat[p * 8 + j] = __float_as_uint(fabsf(base[p * NCH]));

    if (tid < 8) { pref[tid] = 0u; krem[tid] = 2051; }
    __syncthreads();

    for (int pass = 0; pass < 4; ++pass) {
        const int shift = 24 - 8 * pass;
        for (int i = tid; i < 8 * 256; i += 256) cnt[i] = 0u;
        __syncthreads();
        const unsigned int pf = pref[j];
        for (int p = r; p < N1; p += 32) {
            const unsigned int bits = sdat[p * 8 + j];
            const bool ok = (pass == 0) || ((bits >> (shift + 8)) == pf);
            if (ok) atomicAdd(&cnt[j * 256 + ((bits >> shift) & 255u)], 1u);
        }
        __syncthreads();
        if (tid < 8) {
            unsigned int c = 0u;
            const int k = krem[tid];
            const unsigned int p0 = pref[tid];
            for (int bkt = 0; bkt < 256; ++bkt) {
                const unsigned int nc = c + cnt[tid * 256 + bkt];
                if ((unsigned int)k < nc) {
                    pref[tid] = (p0 << 8) | (unsigned int)bkt;
                    krem[tid] = k - (int)c;
                    break;
                }
                c = nc;
            }
        }
        __syncthreads();
    }
    if (tid < 8) {
        const float med = __uint_as_float(pref[tid]);
        g_thr[b * NCH + n0 + tid] = med * THRSCALE;
    }
}

// ---- inverse synthesis: transposed conv, soft-threshold of hi fused --------
__global__ __launch_bounds__(256) void inv_kernel(float* __restrict__ dout, int level) {
    const float* __restrict__ lo;
    const float* __restrict__ hi;
    float* __restrict__ out;
    int n, nout;
    if (level == 3)      { lo = g_lo3; hi = g_hi3; out = g_lo2; n = N3; nout = N2;   }
    else if (level == 2) { lo = g_lo2; hi = g_hi2; out = g_lo1; n = N2; nout = N1;   }
    else                 { lo = g_lo1; hi = g_hi1; out = dout;  n = N1; nout = TLEN; }

    const int b  = blockIdx.y;
    const int nn = threadIdx.x;
    const int j0 = (blockIdx.x * blockDim.y + threadIdx.y) * PJ;
    if (2 * j0 >= nout) return;

    const float thr = g_thr[b * NCH + nn];
    const float DLO[16] = FILT_DLO;
    const float DHI[16] = FILT_DHI;

    const float* __restrict__ lob = lo + (b * n) * NCH + nn;
    const float* __restrict__ hib = hi + (b * n) * NCH + nn;

    float wl[PJ + 7], wh[PJ + 7];
#pragma unroll
    for (int t = 0; t < PJ + 7; ++t) {
        int jj = j0 + t;
        if (jj > n - 1) jj = n - 1;  // clamp: clamped values feed only guarded-off outputs
        wl[t] = lob[jj * NCH];
        const float h = hib[jj * NCH];
        const float a = fabsf(h) - thr;
        wh[t] = (a > 0.f) ? copysignf(a, h) : 0.f;
    }

    const int ob = (b * nout) * NCH + nn;
#pragma unroll
    for (int e = 0; e < PJ; ++e) {
        const int m = 2 * (j0 + e);
        if (m < nout) {
            float a0 = 0.f, a1 = 0.f;
#pragma unroll
            for (int d = 0; d < 8; ++d) {
                a0 += wl[e + d] * DLO[2 * d + 1] + wh[e + d] * DHI[2 * d + 1];
                a1 += wl[e + d] * DLO[2 * d]     + wh[e + d] * DHI[2 * d];
            }
            out[ob + m * NCH] = a0;
            if (m + 1 < nout) out[ob + (m + 1) * NCH] = a1;
        }
    }
}

// ---- launch ----------------------------------------------------------------
extern "C" void kernel_launch(void* const* d_in, const int* in_sizes, int n_in,
                              void* d_out, int out_size) {
    const float* x = (const float*)d_in[0];
    float* out = (float*)d_out;

    // >48KB dynamic smem opt-in (host-side, non-stream, idempotent: capture-safe)
    cudaFuncSetAttribute(med_kernel, cudaFuncAttributeMaxDynamicSharedMemorySize,
                         MED_SMEM_BYTES);

    const dim3 blk(128, 2);
    // forward: grid.x = ceil(nout / (PF*2))
    fwd_kernel<<<dim3(257, BATCH), blk>>>(x, 1);   // 4103 -> 257 tiles of 16
    fwd_kernel<<<dim3(129, BATCH), blk>>>(x, 2);   // 2059
    fwd_kernel<<<dim3( 65, BATCH), blk>>>(x, 3);   // 1037
    med_kernel<<<dim3(16, BATCH), 256, MED_SMEM_BYTES>>>();
    // inverse: grid.x = ceil(ceil(nout/2) / (PJ*2))
    inv_kernel<<<dim3( 65, BATCH), blk>>>(out, 3); // 1030 j -> 65
    inv_kernel<<<dim3(129, BATCH), blk>>>(out, 2); // 2052 j -> 129
    inv_kernel<<<dim3(256, BATCH), blk>>>(out, 1); // 4096 j -> 256
}